// round 13
// baseline (speedup 1.0000x reference)
#include <cuda_runtime.h>
#include <cuda_fp16.h>
#include <cstdint>
#include <math.h>

// LSTM B=128, S=256, I=1024, H=1024. out[b,s,h] fp32.
// Phase 0: prepack x and Wx (x-part of weights) to fp16 device buffers.
// Phase 1: Xp = x @ Wx^T + bias. fp16 mma, 256x128 tiles, cp.async 3-buffer.
// Phase 2: persistent 128-CTA scan (R10 config: pair-scoped pipelines,
//          single-level grid barrier).

#define NBLK2 128
#define WS2_STRIDE 516               // 512 + 4 pad (u32) ; row = 1024 fp16
#define AS2_STRIDE 68                // 64 + 4 pad (u32)  ; row = 128 fp16 chunk
#define PAIR_SLAB (3 * 32 * AS2_STRIDE)
#define RED_OFF   (32 * WS2_STRIDE + 4 * PAIR_SLAB)
#define SMEM2_BYTES ((RED_OFF + 128 * 33) * 4)          // 187,392 B

// phase-1 staging: 3 buffers x (256 A rows + 128 B rows) x 20 u32
// row stride 20 u32 = 80 B (multiple of 16 -> cp.async-legal; banks {0,20,8,28,
// 16,4,24,12} for the 8 fragment rows -> conflict-free)
#define X1_ROWSTRIDE 20
#define X1_BUF (384 * X1_ROWSTRIDE)
#define SMEM1_BYTES (3 * X1_BUF * 4)                    // 92,160 B

__device__ __align__(16) float    g_Xp[(size_t)256 * 128 * 4096];  // 512 MB
__device__ __align__(16) __half   g_h[2 * 128 * 1024];             // h fp16, dbl buf
__device__ __align__(16) __half   g_xh[(size_t)128 * 256 * 1024];  // x in fp16 (64 MB)
__device__ __align__(16) __half   g_wxh[4 * 1024 * 1024];          // Wx fp16 [g][n][k] (8 MB)
__device__ unsigned g_arrive = 0;

__device__ __forceinline__ uint32_t packh2(float a, float b) {
    __half2 h = __floats2half2_rn(a, b);
    return *reinterpret_cast<uint32_t*>(&h);
}

__device__ __forceinline__ void mma_f16(float d[4], const uint32_t a[4], const uint32_t b[2]) {
    asm volatile(
        "mma.sync.aligned.m16n8k16.row.col.f32.f16.f16.f32 "
        "{%0,%1,%2,%3},{%4,%5,%6,%7},{%8,%9},{%0,%1,%2,%3};"
        : "+f"(d[0]), "+f"(d[1]), "+f"(d[2]), "+f"(d[3])
        : "r"(a[0]), "r"(a[1]), "r"(a[2]), "r"(a[3]), "r"(b[0]), "r"(b[1]));
}

__device__ __forceinline__ float sigm(float x) { return 1.0f / (1.0f + expf(-x)); }

// ---------------------------------------------------------------------------
// Phase 0: prepack kernels
// ---------------------------------------------------------------------------
__global__ __launch_bounds__(256) void pack_x_kernel(const float* __restrict__ x) {
    size_t i4 = (size_t)blockIdx.x * 256 + threadIdx.x;   // float4 index
    float4 v = reinterpret_cast<const float4*>(x)[i4];
    uint2 o;
    o.x = packh2(v.x, v.y);
    o.y = packh2(v.z, v.w);
    reinterpret_cast<uint2*>(g_xh)[i4] = o;
}

__global__ __launch_bounds__(256) void pack_w_kernel(
    const float* __restrict__ Wf, const float* __restrict__ Wi,
    const float* __restrict__ Wc, const float* __restrict__ Wo) {
    const float* Wsel[4] = {Wf, Wi, Wc, Wo};
    unsigned i4 = blockIdx.x * 256 + threadIdx.x;         // 0 .. 4*262144-1
    unsigned g = i4 >> 18;
    unsigned rem = i4 & 0x3FFFFu;
    unsigned n = rem >> 8;
    unsigned k4 = (rem & 255u) << 2;
    float4 v = *reinterpret_cast<const float4*>(&Wsel[g][(size_t)n * 2048 + 1024 + k4]);
    uint2 o;
    o.x = packh2(v.x, v.y);
    o.y = packh2(v.z, v.w);
    *reinterpret_cast<uint2*>(&g_wxh[(size_t)g * 1048576 + n * 1024 + k4]) = o;
}

// ---------------------------------------------------------------------------
// Phase 1: 256(m) x 128(n) tiles, BK=32 fp16, 512 thr = 16 warps (4m x 4n),
// warp tile 64x32, cp.async triple-buffered.
// grid: x = 32 n-blocks (gate = bx>>3), y = 128 m-blocks
// ---------------------------------------------------------------------------
__global__ __launch_bounds__(512) void xproj_kernel(
    const float* __restrict__ bf, const float* __restrict__ bi,
    const float* __restrict__ bc, const float* __restrict__ bo)
{
    extern __shared__ uint32_t Sb[];    // [3][384][20]

    const float* bsel[4] = {bf, bi, bc, bo};

    const int tid  = threadIdx.x;
    const int warp = tid >> 5;
    const int lane = tid & 31;
    const int q = lane >> 2, p = lane & 3;
    const int wm = warp >> 2;          // 0..3 (64 rows each)
    const int wn = warp & 3;           // 0..3 (32 cols each)
    const int gate = blockIdx.x >> 3;
    const int r0 = (blockIdx.x & 7) * 128;
    const int m0 = blockIdx.y * 256;
    const float* __restrict__ bg = bsel[gate];
    const __half* __restrict__ wg = &g_wxh[(size_t)gate * 1048576];

    const uint32_t sb_base = (uint32_t)__cvta_generic_to_shared(Sb);

    // copy-op mapping: 1536 x 16B per k-tile (A: 1024 ops, B: 512 ops), 3/thread
    int orow[3], oseg[3]; bool isA[3];
    #pragma unroll
    for (int it = 0; it < 3; ++it) {
        int o = tid + 512 * it;
        if (o < 1024) { isA[it] = true;  orow[it] = o >> 2;          oseg[it] = o & 3; }
        else          { isA[it] = false; orow[it] = (o - 1024) >> 2; oseg[it] = (o - 1024) & 3; }
    }

    float acc[4][4][4];
    #pragma unroll
    for (int mt = 0; mt < 4; ++mt)
        #pragma unroll
        for (int nt = 0; nt < 4; ++nt)
            #pragma unroll
            for (int r = 0; r < 4; ++r) acc[mt][nt][r] = 0.0f;

    // issue k-tiles 0,1
    #pragma unroll
    for (int pc = 0; pc < 2; ++pc) {
        uint32_t boff = (uint32_t)(pc * X1_BUF) << 2;
        #pragma unroll
        for (int it = 0; it < 3; ++it) {
            const __half* src = isA[it]
                ? &g_xh[(size_t)(m0 + orow[it]) * 1024 + pc * 32 + oseg[it] * 8]
                : &wg[(size_t)(r0 + orow[it]) * 1024 + pc * 32 + oseg[it] * 8];
            uint32_t drow = isA[it] ? orow[it] : (256 + orow[it]);
            uint32_t dsm = sb_base + boff + ((drow * X1_ROWSTRIDE + oseg[it] * 4) << 2);
            asm volatile("cp.async.cg.shared.global [%0], [%1], 16;" :: "r"(dsm), "l"(src));
        }
        asm volatile("cp.async.commit_group;");
    }

    for (int c = 0; c < 32; ++c) {
        if (c < 31) { asm volatile("cp.async.wait_group 1;"); }
        else        { asm volatile("cp.async.wait_group 0;"); }
        __syncthreads();

        if (c < 30) {
            int kt = c + 2;
            uint32_t boff = (uint32_t)((kt % 3) * X1_BUF) << 2;
            #pragma unroll
            for (int it = 0; it < 3; ++it) {
                const __half* src = isA[it]
                    ? &g_xh[(size_t)(m0 + orow[it]) * 1024 + kt * 32 + oseg[it] * 8]
                    : &wg[(size_t)(r0 + orow[it]) * 1024 + kt * 32 + oseg[it] * 8];
                uint32_t drow = isA[it] ? orow[it] : (256 + orow[it]);
                uint32_t dsm = sb_base + boff + ((drow * X1_ROWSTRIDE + oseg[it] * 4) << 2);
                asm volatile("cp.async.cg.shared.global [%0], [%1], 16;" :: "r"(dsm), "l"(src));
            }
            asm volatile("cp.async.commit_group;");
        }

        const uint32_t* Ab = Sb + (c % 3) * X1_BUF;
        #pragma unroll
        for (int ks = 0; ks < 2; ++ks) {
            const int au = ks * 8;
            uint32_t a[4][4];
            #pragma unroll
            for (int mt = 0; mt < 4; ++mt) {
                int rb = wm * 64 + mt * 16 + q;
                a[mt][0] = Ab[rb * X1_ROWSTRIDE + au + p];
                a[mt][1] = Ab[(rb + 8) * X1_ROWSTRIDE + au + p];
                a[mt][2] = Ab[rb * X1_ROWSTRIDE + au + p + 4];
                a[mt][3] = Ab[(rb + 8) * X1_ROWSTRIDE + au + p + 4];
            }
            #pragma unroll
            for (int nt = 0; nt < 4; ++nt) {
                uint32_t bb[2];
                int nr = 256 + wn * 32 + nt * 8 + q;
                bb[0] = Ab[nr * X1_ROWSTRIDE + au + p];
                bb[1] = Ab[nr * X1_ROWSTRIDE + au + p + 4];
                #pragma unroll
                for (int mt = 0; mt < 4; ++mt)
                    mma_f16(acc[mt][nt], a[mt], bb);
            }
        }
    }

    #pragma unroll
    for (int mt = 0; mt < 4; ++mt)
        #pragma unroll
        for (int nt = 0; nt < 4; ++nt)
            #pragma unroll
            for (int r = 0; r < 4; ++r) {
                int row = wm * 64 + mt * 16 + q + ((r >> 1) << 3);
                int col = wn * 32 + nt * 8 + 2 * p + (r & 1);
                int m = m0 + row;
                int b = m >> 8;
                int s = m & 255;
                g_Xp[((size_t)(s * 128 + b) * 4096) + gate * 1024 + r0 + col] =
                    acc[mt][nt][r] + bg[r0 + col];
            }
}

// ---------------------------------------------------------------------------
// Phase 2 (R10 configuration)
// ---------------------------------------------------------------------------
__device__ __forceinline__ void grid_barrier() {
    __threadfence();
    __syncthreads();
    if (threadIdx.x == 0) {
        unsigned old = atomicAdd(&g_arrive, 1u);
        unsigned target = (old / gridDim.x + 1u) * gridDim.x;
        while (*(volatile unsigned*)&g_arrive < target) {
            __nanosleep(32);
        }
        __threadfence();
    }
    __syncthreads();
}

__global__ void __launch_bounds__(256, 1) lstm_scan_kernel(
    const float* __restrict__ Wf, const float* __restrict__ Wi,
    const float* __restrict__ Wc, const float* __restrict__ Wo,
    float* __restrict__ out)
{
    extern __shared__ uint8_t smem[];
    uint32_t* Ws  = reinterpret_cast<uint32_t*>(smem);                   // [32][WS2_STRIDE]
    uint32_t* Stg = reinterpret_cast<uint32_t*>(smem) + 32 * WS2_STRIDE; // [4][3][32][AS2_STRIDE]
    float*    red = reinterpret_cast<float*>(smem) + RED_OFF;            // [128][33]

    const float* Wsel[4] = {Wf, Wi, Wc, Wo};
    const int tid  = threadIdx.x;
    const int warp = tid >> 5;
    const int lane = tid & 31;
    const int q = lane >> 2, p = lane & 3;
    const int mg = warp & 3;
    const int km = warp >> 2;
    const int j0 = blockIdx.x * 8;

    uint32_t* slab = Stg + mg * PAIR_SLAB;
    const uint32_t slab_base = (uint32_t)__cvta_generic_to_shared(slab);

    for (int idx = tid; idx < 32 * 256; idx += 256) {
        int cc = idx >> 8;
        int k4 = (idx & 255) * 4;
        int g = cc >> 3, jj = cc & 7;
        const float* Wg = Wsel[g];
        float4 v = *reinterpret_cast<const float4*>(&Wg[(size_t)(j0 + jj) * 2048 + k4]);
        uint32_t* wr = &Ws[cc * WS2_STRIDE + (k4 >> 1)];
        wr[0] = packh2(v.x, v.y);
        wr[1] = packh2(v.z, v.w);
    }
    for (int idx = tid; idx < 1024; idx += 256) {
        int b = idx >> 3, jj = idx & 7;
        g_h[b * 1024 + j0 + jj] = __float2half_rn(0.0f);
    }
    float cst[8];
    #pragma unroll
    for (int i = 0; i < 8; ++i) cst[i] = 0.0f;

    const int tid64 = km * 32 + lane;
    int srow[8], sc4[8];
    #pragma unroll
    for (int it = 0; it < 8; ++it) {
        int idx = tid64 + 64 * it;
        srow[it] = idx >> 4;
        sc4[it]  = (idx & 15) * 4;
    }

    grid_barrier();

    for (int t = 0; t < 256; ++t) {
        const uint32_t* __restrict__ hin =
            reinterpret_cast<const uint32_t*>(&g_h[(t & 1) * (128 * 1024)]);
        __half* __restrict__ hout = &g_h[((t + 1) & 1) * (128 * 1024)];
        const uint32_t* __restrict__ hrow0 = hin + (size_t)(mg * 32) * 512;

        float2 xp[4][4];
        if (km == 0) {
            #pragma unroll
            for (int rr = 0; rr < 4; ++rr) {
                int row = mg * 32 + q + rr * 8;
                size_t base = ((size_t)(t * 128 + row)) * 4096 + j0 + 2 * p;
                #pragma unroll
                for (int g = 0; g < 4; ++g)
                    xp[rr][g] = __ldg(reinterpret_cast<const float2*>(&g_Xp[base + g * 1024]));
            }
        }

        float acc[2][4][4];
        #pragma unroll
        for (int mt = 0; mt < 2; ++mt)
            #pragma unroll
            for (int nt = 0; nt < 4; ++nt)
                #pragma unroll
                for (int r = 0; r < 4; ++r) acc[mt][nt][r] = 0.0f;

        #pragma unroll
        for (int pc = 0; pc < 2; ++pc) {
            uint32_t boff = (uint32_t)(pc * 32 * AS2_STRIDE) << 2;
            #pragma unroll
            for (int it = 0; it < 8; ++it) {
                uint32_t dsm = slab_base + boff + ((srow[it] * AS2_STRIDE + sc4[it]) << 2);
                const uint32_t* src = hrow0 + srow[it] * 512 + pc * 64 + sc4[it];
                asm volatile("cp.async.cg.shared.global [%0], [%1], 16;" :: "r"(dsm), "l"(src));
            }
            asm volatile("cp.async.commit_group;");
        }

        #pragma unroll
        for (int c = 0; c < 8; ++c) {
            if (c < 7) { asm volatile("cp.async.wait_group 1;"); }
            else       { asm volatile("cp.async.wait_group 0;"); }
            asm volatile("bar.sync %0, 64;" :: "r"(1 + mg) : "memory");

            if (c < 6) {
                uint32_t boff = (uint32_t)(((c + 2) % 3) * 32 * AS2_STRIDE) << 2;
                #pragma unroll
                for (int it = 0; it < 8; ++it) {
                    uint32_t dsm = slab_base + boff + ((srow[it] * AS2_STRIDE + sc4[it]) << 2);
                    const uint32_t* src = hrow0 + srow[it] * 512 + (c + 2) * 64 + sc4[it];
                    asm volatile("cp.async.cg.shared.global [%0], [%1], 16;" :: "r"(dsm), "l"(src));
                }
                asm volatile("cp.async.commit_group;");
            }

            const uint32_t* Ab = slab + (c % 3) * (32 * AS2_STRIDE);
            #pragma unroll
            for (int s = 0; s < 4; ++s) {
                const int fi = 2 * s + km;
                const int au = fi * 8 + p;
                const int bu = c * 64 + fi * 8 + p;
                uint32_t a[2][4];
                #pragma unroll
                for (int mt = 0; mt < 2; ++mt) {
                    int rb = mt * 16 + q;
                    a[mt][0] = Ab[rb * AS2_STRIDE + au];
                    a[mt][1] = Ab[(rb + 8) * AS2_STRIDE + au];
                    a[mt][2] = Ab[rb * AS2_STRIDE + au + 4];
                    a[mt][3] = Ab[(rb + 8) * AS2_STRIDE + au + 4];
                }
                #pragma unroll
                for (int nt = 0; nt < 4; ++nt) {
                    uint32_t bb[2];
                    int nr = nt * 8 + q;
                    bb[0] = Ws[nr * WS2_STRIDE + bu];
                    bb[1] = Ws[nr * WS2_STRIDE + bu + 4];
                    mma_f16(acc[0][nt], a[0], bb);
                    mma_f16(acc[1][nt], a[1], bb);
                }
            }
        }

        if (km == 1) {
            float* w = &red[(mg * 32 + lane) * 33];
            #pragma unroll
            for (int mt = 0; mt < 2; ++mt)
                #pragma unroll
                for (int nt = 0; nt < 4; ++nt)
                    #pragma unroll
                    for (int r = 0; r < 4; ++r)
                        w[mt * 16 + nt * 4 + r] = acc[mt][nt][r];
        }
        asm volatile("bar.sync %0, 64;" :: "r"(1 + mg) : "memory");
        if (km == 0) {
            const float* w = &red[(mg * 32 + lane) * 33];
            #pragma unroll
            for (int mt = 0; mt < 2; ++mt)
                #pragma unroll
                for (int nt = 0; nt < 4; ++nt)
                    #pragma unroll
                    for (int r = 0; r < 4; ++r)
                        acc[mt][nt][r] += w[mt * 16 + nt * 4 + r];

            #pragma unroll
            for (int mt = 0; mt < 2; ++mt)
                #pragma unroll
                for (int r = 0; r < 4; ++r) {
                    int rr = mt * 2 + (r >> 1);
                    int row = mg * 32 + q + rr * 8;
                    int jj = 2 * p + (r & 1);
                    float xf = (r & 1) ? xp[rr][0].y : xp[rr][0].x;
                    float xi = (r & 1) ? xp[rr][1].y : xp[rr][1].x;
                    float xg = (r & 1) ? xp[rr][2].y : xp[rr][2].x;
                    float xo = (r & 1) ? xp[rr][3].y : xp[rr][3].x;
                    float fg = sigm(acc[mt][0][r] + xf);
                    float ig = sigm(acc[mt][1][r] + xi);
                    float gg = tanhf(acc[mt][2][r] + xg);
                    float og = sigm(acc[mt][3][r] + xo);
                    float cnew = cst[mt * 4 + r] * fg + ig * gg;
                    cst[mt * 4 + r] = cnew;
                    float hnew = tanhf(cnew) * og;
                    hout[row * 1024 + j0 + jj] = __float2half_rn(hnew);
                    out[(size_t)row * (256 * 1024) + t * 1024 + j0 + jj] = hnew;
                }
        }
        grid_barrier();
    }
}

// ---------------------------------------------------------------------------
extern "C" void kernel_launch(void* const* d_in, const int* in_sizes, int n_in,
                              void* d_out, int out_size) {
    const float* x  = (const float*)d_in[0];
    const float* Wf = (const float*)d_in[1];
    const float* bf = (const float*)d_in[2];
    const float* Wi = (const float*)d_in[3];
    const float* bi = (const float*)d_in[4];
    const float* Wc = (const float*)d_in[5];
    const float* bc = (const float*)d_in[6];
    const float* Wo = (const float*)d_in[7];
    const float* bo = (const float*)d_in[8];
    float* out = (float*)d_out;

    cudaFuncSetAttribute(xproj_kernel,
                         cudaFuncAttributeMaxDynamicSharedMemorySize, SMEM1_BYTES);
    cudaFuncSetAttribute(lstm_scan_kernel,
                         cudaFuncAttributeMaxDynamicSharedMemorySize, SMEM2_BYTES);

    pack_x_kernel<<<32768, 256>>>(x);
    pack_w_kernel<<<4096, 256>>>(Wf, Wi, Wc, Wo);
    dim3 g1(32, 128);
    xproj_kernel<<<g1, 512, SMEM1_BYTES>>>(bf, bi, bc, bo);
    lstm_scan_kernel<<<NBLK2, 256, SMEM2_BYTES>>>(Wf, Wi, Wc, Wo, out);
}

// round 14
// speedup vs baseline: 1.1426x; 1.1426x over previous
#include <cuda_runtime.h>
#include <cuda_fp16.h>
#include <cstdint>
#include <math.h>

// LSTM B=128, S=256, I=1024, H=1024. out[b,s,h] fp32.
// FUSED: single persistent scan kernel computes gates = [h_t | x_t] @ W^T + b
// per step (K=2048). No Xp scratch, no separate projection GEMM.
// Phase 0: pack x to fp16 (one elementwise kernel).
// Scan: 128 CTAs x 256 thr; 4 pairs/CTA (mg) x 2 k-warps (km); pair-private
// triple-buffered cp.async staging; 32 chunks of 64 cols per step.

#define NBLK2 128
#define WS3_STRIDE 1028              // 1024 + 4 pad (u32); row = 2048 fp16
#define ST3_STRIDE 36                // 32 + 4 pad (u32); 144B row, 16B-aligned
#define PAIR_SLAB3 (3 * 32 * ST3_STRIDE)                  // u32
#define RED3_OFF   (32 * WS3_STRIDE + 4 * PAIR_SLAB3)     // u32 offset
#define SMEM3_BYTES ((RED3_OFF + 128 * 33) * 4)           // 203,776 B

__device__ __align__(16) __half   g_h[2 * 128 * 1024];             // h fp16, dbl buf
__device__ __align__(16) __half   g_xh[(size_t)128 * 256 * 1024];  // x fp16 (64 MB)
__device__ unsigned g_arrive = 0;

__device__ __forceinline__ uint32_t packh2(float a, float b) {
    __half2 h = __floats2half2_rn(a, b);
    return *reinterpret_cast<uint32_t*>(&h);
}

__device__ __forceinline__ void mma_f16(float d[4], const uint32_t a[4], const uint32_t b[2]) {
    asm volatile(
        "mma.sync.aligned.m16n8k16.row.col.f32.f16.f16.f32 "
        "{%0,%1,%2,%3},{%4,%5,%6,%7},{%8,%9},{%0,%1,%2,%3};"
        : "+f"(d[0]), "+f"(d[1]), "+f"(d[2]), "+f"(d[3])
        : "r"(a[0]), "r"(a[1]), "r"(a[2]), "r"(a[3]), "r"(b[0]), "r"(b[1]));
}

__device__ __forceinline__ float sigm(float x) { return 1.0f / (1.0f + expf(-x)); }

// ---------------------------------------------------------------------------
// Phase 0: pack x fp32 -> fp16 (layout preserved: [b][s][k])
// ---------------------------------------------------------------------------
__global__ __launch_bounds__(256) void pack_x_kernel(const float* __restrict__ x) {
    size_t i4 = (size_t)blockIdx.x * 256 + threadIdx.x;   // float4 index
    float4 v = reinterpret_cast<const float4*>(x)[i4];
    uint2 o;
    o.x = packh2(v.x, v.y);
    o.y = packh2(v.z, v.w);
    reinterpret_cast<uint2*>(g_xh)[i4] = o;
}

// ---------------------------------------------------------------------------
// Fused persistent scan
// ---------------------------------------------------------------------------
__device__ __forceinline__ void grid_barrier() {
    __threadfence();
    __syncthreads();
    if (threadIdx.x == 0) {
        unsigned old = atomicAdd(&g_arrive, 1u);
        unsigned target = (old / gridDim.x + 1u) * gridDim.x;
        while (*(volatile unsigned*)&g_arrive < target) {
            __nanosleep(32);
        }
        __threadfence();
    }
    __syncthreads();
}

__global__ void __launch_bounds__(256, 1) lstm_scan_kernel(
    const float* __restrict__ Wf, const float* __restrict__ bf,
    const float* __restrict__ Wi, const float* __restrict__ bi,
    const float* __restrict__ Wc, const float* __restrict__ bc,
    const float* __restrict__ Wo, const float* __restrict__ bo,
    float* __restrict__ out)
{
    extern __shared__ uint8_t smem[];
    uint32_t* Ws  = reinterpret_cast<uint32_t*>(smem);                   // [32][WS3_STRIDE]
    uint32_t* Stg = reinterpret_cast<uint32_t*>(smem) + 32 * WS3_STRIDE; // [4][3][32][ST3_STRIDE]
    float*    red = reinterpret_cast<float*>(smem) + RED3_OFF;           // [128][33]

    const float* Wsel[4] = {Wf, Wi, Wc, Wo};
    const float* bsel[4] = {bf, bi, bc, bo};
    const int tid  = threadIdx.x;
    const int warp = tid >> 5;
    const int lane = tid & 31;
    const int q = lane >> 2, p = lane & 3;
    const int mg = warp & 3;     // pair id (32 batches)
    const int km = warp >> 2;    // member in pair (k-interleave)
    const int j0 = blockIdx.x * 8;

    uint32_t* slab = Stg + mg * PAIR_SLAB3;
    const uint32_t slab_base = (uint32_t)__cvta_generic_to_shared(slab);
    const uint32_t* __restrict__ xh32 = reinterpret_cast<const uint32_t*>(g_xh);

    // Load full W slice (rows j0..j0+7 per gate, all 2048 cols: [Wh | Wx]) as fp16
    for (int idx = tid; idx < 32 * 512; idx += 256) {
        int cc = idx >> 9;               // row 0..31 (gate*8 + jj)
        int k4 = (idx & 511) * 4;        // fp32 col 0..2044
        int g = cc >> 3, jj = cc & 7;
        const float* Wg = Wsel[g];
        float4 v = *reinterpret_cast<const float4*>(&Wg[(size_t)(j0 + jj) * 2048 + k4]);
        uint32_t* wr = &Ws[cc * WS3_STRIDE + (k4 >> 1)];
        wr[0] = packh2(v.x, v.y);
        wr[1] = packh2(v.z, v.w);
    }
    for (int idx = tid; idx < 1024; idx += 256) {
        int b = idx >> 3, jj = idx & 7;
        g_h[b * 1024 + j0 + jj] = __float2half_rn(0.0f);
    }
    // bias preload: this thread's 2 columns (jj = 2p, 2p+1) per gate
    float bs[4][2];
    #pragma unroll
    for (int g = 0; g < 4; ++g) {
        bs[g][0] = bsel[g][j0 + 2 * p];
        bs[g][1] = bsel[g][j0 + 2 * p + 1];
    }
    float cst[8];
    #pragma unroll
    for (int i = 0; i < 8; ++i) cst[i] = 0.0f;

    // staging map: pair copies 32 rows x 32 u32 (128B) per chunk; 64 thr x 4 ops
    const int tid64 = km * 32 + lane;
    int srow[4], sseg[4];
    #pragma unroll
    for (int it = 0; it < 4; ++it) {
        int idx = tid64 + 64 * it;       // 0..255
        srow[it] = idx >> 3;             // 0..31 (8 x 16B ops per row)
        sseg[it] = (idx & 7) * 4;        // u32 col in chunk (0..28)
    }

    grid_barrier();

    for (int t = 0; t < 256; ++t) {
        const uint32_t* __restrict__ hin =
            reinterpret_cast<const uint32_t*>(&g_h[(t & 1) * (128 * 1024)]);
        __half* __restrict__ hout = &g_h[((t + 1) & 1) * (128 * 1024)];
        const uint32_t* __restrict__ hrow0 = hin + (size_t)(mg * 32) * 512;

        float acc[2][4][4];
        #pragma unroll
        for (int mt = 0; mt < 2; ++mt)
            #pragma unroll
            for (int nt = 0; nt < 4; ++nt)
                #pragma unroll
                for (int r = 0; r < 4; ++r) acc[mt][nt][r] = 0.0f;

        // prologue: issue chunks 0,1 (both h-side at t start)
        #pragma unroll
        for (int pc = 0; pc < 2; ++pc) {
            uint32_t boff = (uint32_t)(pc * 32 * ST3_STRIDE) << 2;
            #pragma unroll
            for (int it = 0; it < 4; ++it) {
                uint32_t dsm = slab_base + boff + ((srow[it] * ST3_STRIDE + sseg[it]) << 2);
                const uint32_t* src = hrow0 + srow[it] * 512 + pc * 32 + sseg[it];
                asm volatile("cp.async.cg.shared.global [%0], [%1], 16;" :: "r"(dsm), "l"(src));
            }
            asm volatile("cp.async.commit_group;");
        }

        for (int c = 0; c < 32; ++c) {
            if (c < 31) { asm volatile("cp.async.wait_group 1;"); }
            else        { asm volatile("cp.async.wait_group 0;"); }
            asm volatile("bar.sync %0, 64;" :: "r"(1 + mg) : "memory");  // pair barrier

            if (c < 30) {
                int cc = c + 2;
                uint32_t boff = (uint32_t)((cc % 3) * 32 * ST3_STRIDE) << 2;
                #pragma unroll
                for (int it = 0; it < 4; ++it) {
                    uint32_t dsm = slab_base + boff + ((srow[it] * ST3_STRIDE + sseg[it]) << 2);
                    const uint32_t* src;
                    if (cc < 16) {
                        src = hrow0 + srow[it] * 512 + cc * 32 + sseg[it];
                    } else {
                        src = xh32 + ((size_t)(mg * 32 + srow[it]) * 256 + t) * 512
                                   + (cc - 16) * 32 + sseg[it];
                    }
                    asm volatile("cp.async.cg.shared.global [%0], [%1], 16;"
                                 :: "r"(dsm), "l"(src));
                }
                asm volatile("cp.async.commit_group;");
            }

            const uint32_t* Ab = slab + (c % 3) * (32 * ST3_STRIDE);
            #pragma unroll
            for (int s = 0; s < 2; ++s) {
                const int fi = 2 * s + km;              // k16 frag in chunk (0..3)
                const int au = fi * 8 + p;              // u32 col in staging row
                const int bu = c * 32 + fi * 8 + p;     // u32 col in Ws row
                uint32_t a[2][4];
                #pragma unroll
                for (int mt = 0; mt < 2; ++mt) {
                    int rb = mt * 16 + q;
                    a[mt][0] = Ab[rb * ST3_STRIDE + au];
                    a[mt][1] = Ab[(rb + 8) * ST3_STRIDE + au];
                    a[mt][2] = Ab[rb * ST3_STRIDE + au + 4];
                    a[mt][3] = Ab[(rb + 8) * ST3_STRIDE + au + 4];
                }
                #pragma unroll
                for (int nt = 0; nt < 4; ++nt) {
                    uint32_t bb[2];
                    int nr = nt * 8 + q;
                    bb[0] = Ws[nr * WS3_STRIDE + bu];
                    bb[1] = Ws[nr * WS3_STRIDE + bu + 4];
                    mma_f16(acc[0][nt], a[0], bb);
                    mma_f16(acc[1][nt], a[1], bb);
                }
            }
        }

        // 2-way k reduction through dedicated smem (pair-scoped)
        if (km == 1) {
            float* w = &red[(mg * 32 + lane) * 33];
            #pragma unroll
            for (int mt = 0; mt < 2; ++mt)
                #pragma unroll
                for (int nt = 0; nt < 4; ++nt)
                    #pragma unroll
                    for (int r = 0; r < 4; ++r)
                        w[mt * 16 + nt * 4 + r] = acc[mt][nt][r];
        }
        asm volatile("bar.sync %0, 64;" :: "r"(1 + mg) : "memory");
        if (km == 0) {
            const float* w = &red[(mg * 32 + lane) * 33];
            #pragma unroll
            for (int mt = 0; mt < 2; ++mt)
                #pragma unroll
                for (int nt = 0; nt < 4; ++nt)
                    #pragma unroll
                    for (int r = 0; r < 4; ++r)
                        acc[mt][nt][r] += w[mt * 16 + nt * 4 + r];

            #pragma unroll
            for (int mt = 0; mt < 2; ++mt)
                #pragma unroll
                for (int r = 0; r < 4; ++r) {
                    int rr = mt * 2 + (r >> 1);
                    int row = mg * 32 + q + rr * 8;
                    int jj = 2 * p + (r & 1);
                    int e = r & 1;
                    float fg = sigm(acc[mt][0][r] + bs[0][e]);
                    float ig = sigm(acc[mt][1][r] + bs[1][e]);
                    float gg = tanhf(acc[mt][2][r] + bs[2][e]);
                    float og = sigm(acc[mt][3][r] + bs[3][e]);
                    float cnew = cst[mt * 4 + r] * fg + ig * gg;
                    cst[mt * 4 + r] = cnew;
                    float hnew = tanhf(cnew) * og;
                    hout[row * 1024 + j0 + jj] = __float2half_rn(hnew);
                    out[(size_t)row * (256 * 1024) + t * 1024 + j0 + jj] = hnew;
                }
        }
        grid_barrier();
    }
}

// ---------------------------------------------------------------------------
extern "C" void kernel_launch(void* const* d_in, const int* in_sizes, int n_in,
                              void* d_out, int out_size) {
    const float* x  = (const float*)d_in[0];
    const float* Wf = (const float*)d_in[1];
    const float* bf = (const float*)d_in[2];
    const float* Wi = (const float*)d_in[3];
    const float* bi = (const float*)d_in[4];
    const float* Wc = (const float*)d_in[5];
    const float* bc = (const float*)d_in[6];
    const float* Wo = (const float*)d_in[7];
    const float* bo = (const float*)d_in[8];
    float* out = (float*)d_out;

    cudaFuncSetAttribute(lstm_scan_kernel,
                         cudaFuncAttributeMaxDynamicSharedMemorySize, SMEM3_BYTES);

    pack_x_kernel<<<32768, 256>>>(x);
    lstm_scan_kernel<<<NBLK2, 256, SMEM3_BYTES>>>(Wf, bf, Wi, bi, Wc, bc, Wo, bo, out);
}